// round 6
// baseline (speedup 1.0000x reference)
#include <cuda_runtime.h>
#include <cuda_bf16.h>

#define D        512
#define NTAU     100
#define HSLOTS   128           // power-of-2 ring; tag gating + skew<=1 proof => overwrite-safe
#define CTAS     128
#define ROWS     4             // rows (warps) per CTA
#define THREADS  128

// Tagged state ring: word = {hi32: tag = step+1, lo32: float x}.
// Accessed ONLY with relaxed-atomic b64 ops: memory-model-guaranteed
// single-copy atomicity (no tag/payload tearing), no fence cost.
__device__ unsigned long long g_tag[HSLOTS * D];

__device__ __forceinline__ unsigned long long ld_tag(const unsigned long long* p) {
    unsigned long long v;
    asm volatile("ld.relaxed.gpu.global.b64 %0, [%1];" : "=l"(v) : "l"(p) : "memory");
    return v;
}
__device__ __forceinline__ void st_tag(unsigned long long* p, unsigned long long v) {
    asm volatile("st.relaxed.gpu.global.b64 [%0], %1;" :: "l"(p), "l"(v) : "memory");
}

__global__ void reset_kernel() {
    // 256 x 256 = 65536 = HSLOTS * D, one word per thread
    g_tag[blockIdx.x * blockDim.x + threadIdx.x] = 0ULL;
}

__global__ void __launch_bounds__(THREADS, 1) ndde_kernel(
    const float* __restrict__ x0,
    const float* __restrict__ tau,
    const float* __restrict__ W1,
    const float* __restrict__ W2,
    const float* __restrict__ b,
    float* __restrict__ out,
    int N)
{
    const int lane = threadIdx.x & 31;
    const int warp = threadIdx.x >> 5;
    const int row  = blockIdx.x * ROWS + warp;   // this warp's output row
    const long NP1 = (long)N + 1;

    // ---- weights in registers: lane owns k = lane + 32*i, i = 0..15 ----
    float w1r[16], w2r[16];
    #pragma unroll
    for (int i = 0; i < 16; ++i) {
        w1r[i] = W1[row * D + lane + 32 * i];
        w2r[i] = W2[row * D + lane + 32 * i];
    }

    // per-lane partial of W2·x0 (y for all steps j < NTAU)
    float acc_y0 = 0.0f;
    #pragma unroll
    for (int i = 0; i < 16; ++i)
        acc_y0 = fmaf(w2r[i], __ldg(x0 + lane + 32 * i), acc_y0);

    const float dt  = 0.01f * __ldg(tau);
    const float b_r = __ldg(b + row);
    float x_r = __ldg(x0 + row);

    // ---- publish x_0 (slot 0, tag 1) + output column 0 ----
    if (lane == 0) {
        st_tag(&g_tag[row],
               (1ULL << 32) | (unsigned long long)__float_as_uint(x_r));
        out[(long)row * NP1] = x_r;
    }

    float acc_y = acc_y0;   // per-lane partial of W2·y_j for the upcoming step j
    for (int j = 0; j < N; ++j) {
        // ---- x_j load == implicit global barrier (poll tagged words) ----
        const unsigned long long* xs = &g_tag[(j & (HSLOTS - 1)) * D];
        const unsigned xtag = (unsigned)(j + 1);

        unsigned long long vx[16];
        #pragma unroll
        for (int i = 0; i < 16; ++i)
            vx[i] = ld_tag(xs + lane + 32 * i);   // blast, MLP=16

        float a0 = acc_y, a1 = 0.0f;
        #pragma unroll
        for (int i = 0; i < 16; ++i) {
            while ((unsigned)(vx[i] >> 32) < xtag)      // spin on stale words
                vx[i] = ld_tag(xs + lane + 32 * i);
            const float xv = __uint_as_float((unsigned)vx[i]);
            if (i & 1) a1 = fmaf(w1r[i], xv, a1);
            else       a0 = fmaf(w1r[i], xv, a0);
        }
        float acc = a0 + a1;
        #pragma unroll
        for (int off = 16; off; off >>= 1)
            acc += __shfl_xor_sync(0xffffffffu, acc, off);

        // ---- update + publish x_{j+1} (single atomic 8B store, tag j+2) ----
        if (lane == 0) {
            const float z = acc + b_r;                  // bias once, post-reduce
            x_r = fmaf(dt, tanhf(z), x_r);
            st_tag(&g_tag[((j + 1) & (HSLOTS - 1)) * D + row],
                   ((unsigned long long)(unsigned)(j + 2) << 32) |
                   (unsigned long long)__float_as_uint(x_r));
            out[(long)row * NP1 + (j + 1)] = x_r;
        }

        // ---- off-critical-path: per-lane partial of W2·y for step j+1 ----
        const int jn = j + 1;
        if (jn >= NTAU) {
            const unsigned long long* ys = &g_tag[((jn - NTAU) & (HSLOTS - 1)) * D];
            const unsigned ytag = (unsigned)(jn - NTAU + 1);
            unsigned long long vy[16];
            #pragma unroll
            for (int i = 0; i < 16; ++i)
                vy[i] = ld_tag(ys + lane + 32 * i);
            float y0 = 0.0f, y1 = 0.0f;
            #pragma unroll
            for (int i = 0; i < 16; ++i) {
                while ((unsigned)(vy[i] >> 32) < ytag)  // ~never spins (100 steps old)
                    vy[i] = ld_tag(ys + lane + 32 * i);
                const float yv = __uint_as_float((unsigned)vy[i]);
                if (i & 1) y1 = fmaf(w2r[i], yv, y1);
                else       y0 = fmaf(w2r[i], yv, y0);
            }
            acc_y = y0 + y1;
        } else {
            acc_y = acc_y0;
        }
    }
}

extern "C" void kernel_launch(void* const* d_in, const int* in_sizes, int n_in,
                              void* d_out, int out_size) {
    const float* x0  = (const float*)d_in[0];
    const float* tau = (const float*)d_in[1];
    const float* W1  = (const float*)d_in[2];
    const float* W2  = (const float*)d_in[3];
    const float* b   = (const float*)d_in[4];
    float* out = (float*)d_out;

    const int N = out_size / D - 1;    // out is [D, N+1]

    reset_kernel<<<256, 256>>>();      // zero all tags (graph-replay determinism)
    ndde_kernel<<<CTAS, THREADS>>>(x0, tau, W1, W2, b, out, N);
}

// round 7
// speedup vs baseline: 3.4356x; 3.4356x over previous
#include <cuda_runtime.h>
#include <cuda_bf16.h>

#define D        512
#define NTAU     100
#define HSLOTS   128           // ring; flag-gated skew<=1 => overwrite-safe (26-step margin)
#define CTAS     128
#define ROWS     4             // one row per warp
#define THREADS  128
#define NFLAGS   (CTAS * ROWS) // 512

// Persistent device state (no allocations allowed).
__device__ __align__(16) float g_x[HSLOTS * D];   // plain float state ring
__device__ __align__(16) int   g_flag[NFLAGS];    // g_flag[r] = latest step published by row r

__global__ void reset_kernel() { g_flag[threadIdx.x] = 0; }   // <<<1, 512>>>

// Volatile vectorized flag sweep: one LDG.128 per lane covers 4 flags;
// 32 lanes cover all 512. "memory"+volatile stop CSE/hoisting of the spin.
__device__ __forceinline__ int4 ld_flags4(const int4* p) {
    int4 v;
    asm volatile("ld.global.cg.v4.b32 {%0,%1,%2,%3}, [%4];"
                 : "=r"(v.x), "=r"(v.y), "=r"(v.z), "=r"(v.w) : "l"(p) : "memory");
    return v;
}

__global__ void __launch_bounds__(THREADS, 1) ndde_kernel(
    const float* __restrict__ x0,
    const float* __restrict__ tau,
    const float* __restrict__ W1,
    const float* __restrict__ W2,
    const float* __restrict__ b,
    float* __restrict__ out,
    int N)
{
    const int lane = threadIdx.x & 31;
    const int warp = threadIdx.x >> 5;
    const int row  = blockIdx.x * ROWS + warp;    // this warp's output row
    const long NP1 = (long)N + 1;

    // ---- prologue: publish x_0 ASAP so peers can start ----
    float x_r = __ldg(x0 + row);
    if (lane == 0) {
        __stcg(&g_x[row], x_r);                   // slot 0
        __threadfence();                          // release
        __stcg(&g_flag[row], 1);
        out[(long)row * NP1] = x_r;               // column 0
    }

    // ---- weights in registers, float4 layout: k = g*128 + 4*lane + c ----
    const float4* W1v = (const float4*)(W1 + (long)row * D);
    const float4* W2v = (const float4*)(W2 + (long)row * D);
    float4 w1q[4], w2q[4];
    #pragma unroll
    for (int g = 0; g < 4; ++g) {
        w1q[g] = __ldg(W1v + g * 32 + lane);
        w2q[g] = __ldg(W2v + g * 32 + lane);
    }

    // per-lane partial of W2·x0  (y_j = x_0 for all j < NTAU)
    const float4* X0v = (const float4*)x0;
    float acc_y0 = 0.0f;
    #pragma unroll
    for (int g = 0; g < 4; ++g) {
        const float4 xq = __ldg(X0v + g * 32 + lane);
        acc_y0 = fmaf(w2q[g].x, xq.x, acc_y0);
        acc_y0 = fmaf(w2q[g].y, xq.y, acc_y0);
        acc_y0 = fmaf(w2q[g].z, xq.z, acc_y0);
        acc_y0 = fmaf(w2q[g].w, xq.w, acc_y0);
    }

    const float dt  = 0.01f * __ldg(tau);
    const float b_r = __ldg(b + row);
    const int4* fp  = ((const int4*)g_flag) + lane;

    float acc_y = acc_y0;      // per-lane partial of W2·y_j for upcoming step j
    for (int j = 0; j < N; ++j) {
        // ---- wait: all 512 rows published x_j (flags >= j+1) ----
        const int need = j + 1;
        int4 f = ld_flags4(fp);
        while (!__all_sync(0xffffffffu,
                           (f.x >= need) & (f.y >= need) &
                           (f.z >= need) & (f.w >= need))) {
            __nanosleep(32);                      // herd damping
            f = ld_flags4(fp);
        }
        __threadfence();                          // acquire

        // ---- acc = W1[row]·x_j + acc_y  (vectorized, dual accumulators) ----
        const float4* xv = (const float4*)(g_x + (size_t)(j & (HSLOTS - 1)) * D);
        float4 xq[4];
        #pragma unroll
        for (int g = 0; g < 4; ++g)
            xq[g] = __ldcg(xv + g * 32 + lane);   // blast, MLP=4x128b
        float a0 = acc_y, a1 = 0.0f;
        #pragma unroll
        for (int g = 0; g < 4; ++g) {
            a0 = fmaf(w1q[g].x, xq[g].x, a0);
            a1 = fmaf(w1q[g].y, xq[g].y, a1);
            a0 = fmaf(w1q[g].z, xq[g].z, a0);
            a1 = fmaf(w1q[g].w, xq[g].w, a1);
        }
        float acc = a0 + a1;
        #pragma unroll
        for (int off = 16; off; off >>= 1)
            acc += __shfl_xor_sync(0xffffffffu, acc, off);

        // ---- update + publish x_{j+1}: data -> fence -> flag ----
        if (lane == 0) {
            const float z = acc + b_r;            // bias once, post-reduce
            x_r = fmaf(dt, tanhf(z), x_r);
            __stcg(&g_x[(size_t)((j + 1) & (HSLOTS - 1)) * D + row], x_r);
            __threadfence();                      // release
            __stcg(&g_flag[row], j + 2);
            out[(long)row * NP1 + (j + 1)] = x_r; // off-path trajectory store
        }

        // ---- off-critical-path: per-lane partial of W2·y for step j+1 ----
        // y_{j+1} = x_{j+1-NTAU}: 100 steps old, flag-checked long ago -> plain read.
        const int jn = j + 1;
        if (jn >= NTAU) {
            const float4* yv =
                (const float4*)(g_x + (size_t)((jn - NTAU) & (HSLOTS - 1)) * D);
            float y0 = 0.0f, y1 = 0.0f;
            #pragma unroll
            for (int g = 0; g < 4; ++g) {
                const float4 yq = __ldcg(yv + g * 32 + lane);
                y0 = fmaf(w2q[g].x, yq.x, y0);
                y1 = fmaf(w2q[g].y, yq.y, y1);
                y0 = fmaf(w2q[g].z, yq.z, y0);
                y1 = fmaf(w2q[g].w, yq.w, y1);
            }
            acc_y = y0 + y1;
        } else {
            acc_y = acc_y0;
        }
    }
}

extern "C" void kernel_launch(void* const* d_in, const int* in_sizes, int n_in,
                              void* d_out, int out_size) {
    const float* x0  = (const float*)d_in[0];
    const float* tau = (const float*)d_in[1];
    const float* W1  = (const float*)d_in[2];
    const float* W2  = (const float*)d_in[3];
    const float* b   = (const float*)d_in[4];
    float* out = (float*)d_out;

    const int N = out_size / D - 1;    // out is [D, N+1]

    reset_kernel<<<1, NFLAGS>>>();     // zero flags (graph-replay determinism)
    ndde_kernel<<<CTAS, THREADS>>>(x0, tau, W1, W2, b, out, N);
}

// round 8
// speedup vs baseline: 3.7694x; 1.0972x over previous
#include <cuda_runtime.h>
#include <cuda_bf16.h>

#define D        512
#define NTAU     100
#define HSLOTS   128                 // ring; tag gating + skew<=1 => overwrite-safe
#define CTAS     32
#define ROWS     16                  // compute warps (rows) per CTA
#define THREADS  ((ROWS + 1) * 32)   // 544: 16 compute warps + 1 poller warp

// Tagged state ring: word = {hi32: tag = step+1, lo32: float x}.
// Relaxed-atomic b64 => single-copy atomic (no tag/payload tearing; proven R6).
__device__ unsigned long long g_tag[HSLOTS * D];

__device__ __forceinline__ unsigned long long ld_tag(const unsigned long long* p) {
    unsigned long long v;
    asm volatile("ld.relaxed.gpu.global.b64 %0, [%1];" : "=l"(v) : "l"(p) : "memory");
    return v;
}
__device__ __forceinline__ void st_tag(unsigned long long* p, unsigned long long v) {
    asm volatile("st.relaxed.gpu.global.b64 [%0], %1;" :: "l"(p), "l"(v) : "memory");
}

__global__ void reset_kernel() {       // <<<256, 256>>> covers HSLOTS*D words
    g_tag[blockIdx.x * blockDim.x + threadIdx.x] = 0ULL;
}

__global__ void __launch_bounds__(THREADS, 1) ndde_kernel(
    const float* __restrict__ x0,
    const float* __restrict__ tau,
    const float* __restrict__ W1,
    const float* __restrict__ W2,
    const float* __restrict__ b,
    float* __restrict__ out,
    int N)
{
    __shared__ __align__(16) float sx[2][D];   // double-buffered x_j tile

    const int  lane = threadIdx.x & 31;
    const int  warp = threadIdx.x >> 5;
    const bool comp = (warp < ROWS);
    const int  row  = blockIdx.x * ROWS + warp;  // valid when comp
    const long NP1  = (long)N + 1;

    float x_r = 0.0f, b_r = 0.0f, dt = 0.0f, acc_y0 = 0.0f;
    float4 w1q[4];      // float4 layout: k = 128g + 4*lane + c   (x path, smem)
    float  w2r[16];     // strided layout: k = lane + 32*i        (y path, gmem)

    if (comp) {
        // publish x_0 FIRST so peers can start while we load weights
        x_r = __ldg(x0 + row);
        if (lane == 0) {
            st_tag(&g_tag[row],
                   (1ULL << 32) | (unsigned long long)__float_as_uint(x_r));
            out[(long)row * NP1] = x_r;
        }
        const float4* W1v = (const float4*)(W1 + (long)row * D);
        #pragma unroll
        for (int g = 0; g < 4; ++g) w1q[g] = __ldg(W1v + g * 32 + lane);
        #pragma unroll
        for (int i = 0; i < 16; ++i) w2r[i] = W2[(long)row * D + lane + 32 * i];

        #pragma unroll
        for (int i = 0; i < 16; ++i)   // W2·x0 partial (y for j < NTAU)
            acc_y0 = fmaf(w2r[i], __ldg(x0 + lane + 32 * i), acc_y0);

        dt  = 0.01f * __ldg(tau);
        b_r = __ldg(b + row);
    }

    float acc_y = acc_y0;   // per-lane partial of W2·y_j for upcoming step j
    for (int j = 0; j < N; ++j) {
        // ---- poller warp: gather all 512 tagged words for step j into smem ----
        if (warp == ROWS) {
            const unsigned long long* xs = &g_tag[(size_t)(j & (HSLOTS - 1)) * D];
            const unsigned need = (unsigned)(j + 1);
            unsigned long long v[16];
            #pragma unroll
            for (int i = 0; i < 16; ++i)
                v[i] = ld_tag(xs + lane + 32 * i);        // blast, MLP=16
            #pragma unroll
            for (int i = 0; i < 16; ++i) {
                while ((unsigned)(v[i] >> 32) < need)     // reload only stale
                    v[i] = ld_tag(xs + lane + 32 * i);
                sx[j & 1][lane + 32 * i] = __uint_as_float((unsigned)v[i]);
            }
        }
        __syncthreads();   // hands sx[j&1] to compute warps (CTA happens-before)

        if (comp) {
            // ---- acc = W1[row]·x_j + acc_y  (smem x, dual accumulators) ----
            const float4* xv = (const float4*)sx[j & 1];
            float4 xq[4];
            #pragma unroll
            for (int g = 0; g < 4; ++g) xq[g] = xv[g * 32 + lane];
            float a0 = acc_y, a1 = 0.0f;
            #pragma unroll
            for (int g = 0; g < 4; ++g) {
                a0 = fmaf(w1q[g].x, xq[g].x, a0);
                a1 = fmaf(w1q[g].y, xq[g].y, a1);
                a0 = fmaf(w1q[g].z, xq[g].z, a0);
                a1 = fmaf(w1q[g].w, xq[g].w, a1);
            }
            float acc = a0 + a1;
            #pragma unroll
            for (int off = 16; off; off >>= 1)
                acc += __shfl_xor_sync(0xffffffffu, acc, off);

            // ---- update + publish x_{j+1} (one 8B relaxed store, tag j+2) ----
            if (lane == 0) {
                const float z = acc + b_r;                // bias once, post-reduce
                x_r = fmaf(dt, tanhf(z), x_r);
                st_tag(&g_tag[(size_t)((j + 1) & (HSLOTS - 1)) * D + row],
                       ((unsigned long long)(unsigned)(j + 2) << 32) |
                       (unsigned long long)__float_as_uint(x_r));
                out[(long)row * NP1 + (j + 1)] = x_r;     // no fence path
            }

            // ---- off-critical-path: W2·y partial for step j+1 ----
            // y_{j+1} = x_{j+1-NTAU}: 100 steps old, transitively gated by the
            // poller => written & stable; payload-only read, overlaps poll wait.
            const int jn = j + 1;
            if (jn >= NTAU) {
                const unsigned long long* ys =
                    &g_tag[(size_t)((jn - NTAU) & (HSLOTS - 1)) * D];
                float y0 = 0.0f, y1 = 0.0f;
                #pragma unroll
                for (int i = 0; i < 16; ++i) {
                    const float yv =
                        __uint_as_float((unsigned)ld_tag(ys + lane + 32 * i));
                    if (i & 1) y1 = fmaf(w2r[i], yv, y1);
                    else       y0 = fmaf(w2r[i], yv, y0);
                }
                acc_y = y0 + y1;
            } else {
                acc_y = acc_y0;
            }
        }
    }
}

extern "C" void kernel_launch(void* const* d_in, const int* in_sizes, int n_in,
                              void* d_out, int out_size) {
    const float* x0  = (const float*)d_in[0];
    const float* tau = (const float*)d_in[1];
    const float* W1  = (const float*)d_in[2];
    const float* W2  = (const float*)d_in[3];
    const float* b   = (const float*)d_in[4];
    float* out = (float*)d_out;

    const int N = out_size / D - 1;    // out is [D, N+1]

    reset_kernel<<<256, 256>>>();      // zero tags (graph-replay determinism)
    ndde_kernel<<<CTAS, THREADS>>>(x0, tau, W1, W2, b, out, N);
}

// round 9
// speedup vs baseline: 12.1260x; 3.2170x over previous
#include <cuda_runtime.h>
#include <cuda_bf16.h>

#define D        512
#define NTAU     100
#define HSLOTS   128                 // ring; tag gating + skew<=1 => overwrite-safe
#define CTAS     32
#define ROWS     16                  // compute warps (rows) per CTA
#define THREADS  ((ROWS + 1) * 32)   // 544: 16 compute warps + 1 poller warp

// Tagged state ring: word = {hi32: tag = step+1, lo32: float x}.
// Relaxed-atomic b64 => single-copy atomic (no tag/payload tearing; proven R6/R8).
__device__ unsigned long long g_tag[HSLOTS * D];

__device__ __forceinline__ unsigned long long ld_tag(const unsigned long long* p) {
    unsigned long long v;
    asm volatile("ld.relaxed.gpu.global.b64 %0, [%1];" : "=l"(v) : "l"(p) : "memory");
    return v;
}
__device__ __forceinline__ void st_tag(unsigned long long* p, unsigned long long v) {
    asm volatile("st.relaxed.gpu.global.b64 [%0], %1;" :: "l"(p), "l"(v) : "memory");
}
// Payload-only read (low 4B of the little-endian 8B word). .cg never fills L1,
// so a 100-step-old published value is always read from coherent L2.
__device__ __forceinline__ float ld_payload(const unsigned long long* p) {
    float v;
    asm volatile("ld.global.cg.f32 %0, [%1];" : "=f"(v) : "l"(p) : "memory");
    return v;
}

__global__ void reset_kernel() {       // <<<256, 256>>> covers HSLOTS*D words
    g_tag[blockIdx.x * blockDim.x + threadIdx.x] = 0ULL;
}

__global__ void __launch_bounds__(THREADS, 1) ndde_kernel(
    const float* __restrict__ x0,
    const float* __restrict__ tau,
    const float* __restrict__ W1,
    const float* __restrict__ W2,
    const float* __restrict__ b,
    float* __restrict__ out,
    int N)
{
    __shared__ __align__(16) float sx[2][D];   // double-buffered x_j tile

    const int  lane = threadIdx.x & 31;
    const int  warp = threadIdx.x >> 5;
    const bool comp = (warp < ROWS);
    const int  row  = blockIdx.x * ROWS + warp;  // valid when comp
    const long NP1  = (long)N + 1;

    float x_r = 0.0f, b_r = 0.0f, dt = 0.0f, acc_y0 = 0.0f;
    float4 w1q[4];      // float4 layout: k = 128g + 4*lane + c   (x path, smem)
    float  w2r[16];     // strided layout: k = lane + 32*i        (y path, gmem)

    if (comp) {
        // publish x_0 FIRST so peers can start while we load weights
        x_r = __ldg(x0 + row);
        if (lane == 0) {
            st_tag(&g_tag[row],
                   (1ULL << 32) | (unsigned long long)__float_as_uint(x_r));
            out[(long)row * NP1] = x_r;
        }
        const float4* W1v = (const float4*)(W1 + (long)row * D);
        #pragma unroll
        for (int g = 0; g < 4; ++g) w1q[g] = __ldg(W1v + g * 32 + lane);
        #pragma unroll
        for (int i = 0; i < 16; ++i) w2r[i] = W2[(long)row * D + lane + 32 * i];

        #pragma unroll
        for (int i = 0; i < 16; ++i)   // W2·x0 partial (y for j < NTAU)
            acc_y0 = fmaf(w2r[i], __ldg(x0 + lane + 32 * i), acc_y0);

        dt  = 0.01f * __ldg(tau);
        b_r = __ldg(b + row);
    }

    float acc_y = acc_y0;   // per-lane partial of W2·y_j for upcoming step j
    for (int j = 0; j < N; ++j) {
        // ---- poller warp: gather all 512 tagged words for step j into smem ----
        // PARALLEL retry: each round reloads ALL stale words concurrently
        // (independent loads, MLP = stale count) — no serial spin chains.
        if (warp == ROWS) {
            const unsigned long long* xs = &g_tag[(size_t)(j & (HSLOTS - 1)) * D];
            const unsigned need = (unsigned)(j + 1);
            unsigned long long v[16];
            unsigned stale = 0xFFFFu;
            do {
                #pragma unroll
                for (int i = 0; i < 16; ++i)
                    if (stale & (1u << i))
                        v[i] = ld_tag(xs + lane + 32 * i);
                #pragma unroll
                for (int i = 0; i < 16; ++i)
                    if ((stale & (1u << i)) && (unsigned)(v[i] >> 32) >= need)
                        stale &= ~(1u << i);
            } while (stale);
            #pragma unroll
            for (int i = 0; i < 16; ++i)
                sx[j & 1][lane + 32 * i] = __uint_as_float((unsigned)v[i]);
        }
        __syncthreads();   // hands sx[j&1] to compute warps (CTA happens-before)

        if (comp) {
            // ---- acc = W1[row]·x_j + acc_y  (smem x, dual accumulators) ----
            const float4* xv = (const float4*)sx[j & 1];
            float4 xq[4];
            #pragma unroll
            for (int g = 0; g < 4; ++g) xq[g] = xv[g * 32 + lane];
            float a0 = acc_y, a1 = 0.0f;
            #pragma unroll
            for (int g = 0; g < 4; ++g) {
                a0 = fmaf(w1q[g].x, xq[g].x, a0);
                a1 = fmaf(w1q[g].y, xq[g].y, a1);
                a0 = fmaf(w1q[g].z, xq[g].z, a0);
                a1 = fmaf(w1q[g].w, xq[g].w, a1);
            }
            float acc = a0 + a1;
            #pragma unroll
            for (int off = 16; off; off >>= 1)
                acc += __shfl_xor_sync(0xffffffffu, acc, off);

            // ---- update + publish x_{j+1} (one 8B relaxed store, tag j+2) ----
            if (lane == 0) {
                const float z = acc + b_r;                // bias once, post-reduce
                x_r = fmaf(dt, tanhf(z), x_r);
                st_tag(&g_tag[(size_t)((j + 1) & (HSLOTS - 1)) * D + row],
                       ((unsigned long long)(unsigned)(j + 2) << 32) |
                       (unsigned long long)__float_as_uint(x_r));
            }

            // ---- off-critical-path: W2·y partial for step j+1 ----
            // y_{j+1} = x_{j+1-NTAU}: 100 steps old, transitively gated by the
            // poller => stable; payload-only 32-bit reads, overlaps poll wait.
            const int jn = j + 1;
            if (jn >= NTAU) {
                const unsigned long long* ys =
                    &g_tag[(size_t)((jn - NTAU) & (HSLOTS - 1)) * D];
                float y0 = 0.0f, y1 = 0.0f;
                #pragma unroll
                for (int i = 0; i < 16; ++i) {
                    const float yv = ld_payload(ys + lane + 32 * i);
                    if (i & 1) y1 = fmaf(w2r[i], yv, y1);
                    else       y0 = fmaf(w2r[i], yv, y0);
                }
                acc_y = y0 + y1;
            } else {
                acc_y = acc_y0;
            }

            if (lane == 0)
                out[(long)row * NP1 + (j + 1)] = x_r;     // fully off-path
        }
    }
}

extern "C" void kernel_launch(void* const* d_in, const int* in_sizes, int n_in,
                              void* d_out, int out_size) {
    const float* x0  = (const float*)d_in[0];
    const float* tau = (const float*)d_in[1];
    const float* W1  = (const float*)d_in[2];
    const float* W2  = (const float*)d_in[3];
    const float* b   = (const float*)d_in[4];
    float* out = (float*)d_out;

    const int N = out_size / D - 1;    // out is [D, N+1]

    reset_kernel<<<256, 256>>>();      // zero tags (graph-replay determinism)
    ndde_kernel<<<CTAS, THREADS>>>(x0, tau, W1, W2, b, out, N);
}

// round 10
// speedup vs baseline: 12.1699x; 1.0036x over previous
#include <cuda_runtime.h>
#include <cuda_bf16.h>

#define D        512
#define NTAU     100
#define HSLOTS   128                 // ring; tag gating + skew<=1 => overwrite-safe
#define CTAS     32
#define ROWS     16                  // compute warps (rows) per CTA
#define THREADS  ((ROWS + 1) * 32)   // 544: 16 compute warps + 1 poller warp

// Tagged state ring: word = {hi32: tag = step+1, lo32: float x}.
// Relaxed-atomic b64 => single-copy atomic (no tag/payload tearing; proven R6/R8/R9).
__device__ unsigned long long g_tag[HSLOTS * D];

__device__ __forceinline__ unsigned long long ld_tag(const unsigned long long* p) {
    unsigned long long v;
    asm volatile("ld.relaxed.gpu.global.b64 %0, [%1];" : "=l"(v) : "l"(p) : "memory");
    return v;
}
__device__ __forceinline__ void st_tag(unsigned long long* p, unsigned long long v) {
    asm volatile("st.relaxed.gpu.global.b64 [%0], %1;" :: "l"(p), "l"(v) : "memory");
}
// Payload-only read (low 4B of the little-endian 8B word). .cg never fills L1,
// so a 100-step-old published value is always read from coherent L2.
__device__ __forceinline__ float ld_payload(const unsigned long long* p) {
    float v;
    asm volatile("ld.global.cg.f32 %0, [%1];" : "=f"(v) : "l"(p) : "memory");
    return v;
}

// Producer/consumer named barrier: poller arrives (never waits), compute syncs.
#define TILE_ARRIVE() asm volatile("bar.arrive 1, %0;" :: "n"(THREADS) : "memory")
#define TILE_WAIT()   asm volatile("bar.sync   1, %0;" :: "n"(THREADS) : "memory")

__global__ void reset_kernel() {       // <<<256, 256>>> covers HSLOTS*D words
    g_tag[blockIdx.x * blockDim.x + threadIdx.x] = 0ULL;
}

__global__ void __launch_bounds__(THREADS, 1) ndde_kernel(
    const float* __restrict__ x0,
    const float* __restrict__ tau,
    const float* __restrict__ W1,
    const float* __restrict__ W2,
    const float* __restrict__ b,
    float* __restrict__ out,
    int N)
{
    __shared__ __align__(16) float sx[2][D];   // double-buffered x_j tile

    const int  lane = threadIdx.x & 31;
    const int  warp = threadIdx.x >> 5;
    const bool comp = (warp < ROWS);
    const int  row  = blockIdx.x * ROWS + warp;  // valid when comp
    const long NP1  = (long)N + 1;

    if (!comp) {
        // ================= POLLER WARP =================
        // Per step: gather 512 tagged words (parallel retry), deposit payloads
        // into sx[j&1], arrive on the tile barrier, move on. Never waits on
        // compute warps — WAR on the double buffer is excluded by tag gating.
        for (int j = 0; j < N; ++j) {
            const unsigned long long* xs = &g_tag[(size_t)(j & (HSLOTS - 1)) * D];
            const unsigned need = (unsigned)(j + 1);
            unsigned long long v[16];
            unsigned stale = 0xFFFFu;
            do {
                #pragma unroll
                for (int i = 0; i < 16; ++i)
                    if (stale & (1u << i))
                        v[i] = ld_tag(xs + lane + 32 * i);   // parallel reloads
                #pragma unroll
                for (int i = 0; i < 16; ++i)
                    if ((stale & (1u << i)) && (unsigned)(v[i] >> 32) >= need)
                        stale &= ~(1u << i);
            } while (stale);
            #pragma unroll
            for (int i = 0; i < 16; ++i)
                sx[j & 1][lane + 32 * i] = __uint_as_float((unsigned)v[i]);
            TILE_ARRIVE();                       // release tile j to compute
        }
        return;
    }

    // ================= COMPUTE WARPS (one row each) =================
    // publish x_0 FIRST so peers can start while we load weights
    float x_r = __ldg(x0 + row);
    if (lane == 0) {
        st_tag(&g_tag[row],
               (1ULL << 32) | (unsigned long long)__float_as_uint(x_r));
        out[(long)row * NP1] = x_r;
    }

    float4 w1q[4];      // float4 layout: k = 128g + 4*lane + c   (x path, smem)
    float  w2r[16];     // strided layout: k = lane + 32*i        (y path, gmem)
    const float4* W1v = (const float4*)(W1 + (long)row * D);
    #pragma unroll
    for (int g = 0; g < 4; ++g) w1q[g] = __ldg(W1v + g * 32 + lane);
    #pragma unroll
    for (int i = 0; i < 16; ++i) w2r[i] = W2[(long)row * D + lane + 32 * i];

    float acc_y0 = 0.0f;
    #pragma unroll
    for (int i = 0; i < 16; ++i)       // W2·x0 partial (y for j < NTAU)
        acc_y0 = fmaf(w2r[i], __ldg(x0 + lane + 32 * i), acc_y0);

    const float dt  = 0.01f * __ldg(tau);
    const float b_r = __ldg(b + row);

    float acc_y = acc_y0;   // per-lane partial of W2·y_j for upcoming step j
    for (int j = 0; j < N; ++j) {
        TILE_WAIT();                             // wait ONLY for the poller

        // ---- acc = W1[row]·x_j + acc_y  (smem x, dual accumulators) ----
        const float4* xv = (const float4*)sx[j & 1];
        float4 xq[4];
        #pragma unroll
        for (int g = 0; g < 4; ++g) xq[g] = xv[g * 32 + lane];
        float a0 = acc_y, a1 = 0.0f;
        #pragma unroll
        for (int g = 0; g < 4; ++g) {
            a0 = fmaf(w1q[g].x, xq[g].x, a0);
            a1 = fmaf(w1q[g].y, xq[g].y, a1);
            a0 = fmaf(w1q[g].z, xq[g].z, a0);
            a1 = fmaf(w1q[g].w, xq[g].w, a1);
        }
        float acc = a0 + a1;
        #pragma unroll
        for (int off = 16; off; off >>= 1)
            acc += __shfl_xor_sync(0xffffffffu, acc, off);

        // ---- update + publish x_{j+1} (one 8B relaxed store, tag j+2) ----
        if (lane == 0) {
            const float z = acc + b_r;           // bias once, post-reduce
            x_r = fmaf(dt, tanhf(z), x_r);
            st_tag(&g_tag[(size_t)((j + 1) & (HSLOTS - 1)) * D + row],
                   ((unsigned long long)(unsigned)(j + 2) << 32) |
                   (unsigned long long)__float_as_uint(x_r));
        }

        // ---- tail (overlaps poller's next discovery): W2·y + out store ----
        const int jn = j + 1;
        if (jn >= NTAU) {
            const unsigned long long* ys =
                &g_tag[(size_t)((jn - NTAU) & (HSLOTS - 1)) * D];
            float y0 = 0.0f, y1 = 0.0f;
            #pragma unroll
            for (int i = 0; i < 16; ++i) {
                const float yv = ld_payload(ys + lane + 32 * i);
                if (i & 1) y1 = fmaf(w2r[i], yv, y1);
                else       y0 = fmaf(w2r[i], yv, y0);
            }
            acc_y = y0 + y1;
        } else {
            acc_y = acc_y0;
        }

        if (lane == 0)
            out[(long)row * NP1 + (j + 1)] = x_r;
    }
}

extern "C" void kernel_launch(void* const* d_in, const int* in_sizes, int n_in,
                              void* d_out, int out_size) {
    const float* x0  = (const float*)d_in[0];
    const float* tau = (const float*)d_in[1];
    const float* W1  = (const float*)d_in[2];
    const float* W2  = (const float*)d_in[3];
    const float* b   = (const float*)d_in[4];
    float* out = (float*)d_out;

    const int N = out_size / D - 1;    // out is [D, N+1]

    reset_kernel<<<256, 256>>>();      // zero tags (graph-replay determinism)
    ndde_kernel<<<CTAS, THREADS>>>(x0, tau, W1, W2, b, out, N);
}